// round 8
// baseline (speedup 1.0000x reference)
#include <cuda_runtime.h>
#include <stdint.h>

// BNB 8-bit embedding dequant gather (harness materializes int8 q_weight as int32):
//   out[token,:] = (float)q_weight[x[token],:] * (absmax[x[token]] / 127)
// x[32768] i32, q_weight[50257,1024] i32, absmax[50257] f32, out[32768,1024] f32.
//
// Persistent software-pipelined version: each CTA grid-strides over batches of
// 4 tokens, prefetching batch k+1's gathers while batch k converts/stores.
// Goal: keep read requests in flight continuously (no per-CTA head/tail
// bubbles), holding in-flight bytes high without occupancy collapse.

static constexpr int DIM = 1024;
static constexpr int THREADS = 256;   // DIM/4 int4 lanes
static constexpr int BATCH = 4;
static constexpr int CTAS = 148 * 8;  // persistent-ish: ~8 CTAs/SM

__global__ __launch_bounds__(THREADS)
void bnb8_embed_kernel(const int* __restrict__ x,
                       const int* __restrict__ qw,
                       const float* __restrict__ absmax,
                       float* __restrict__ out,
                       int n_tokens)
{
    const int stride = gridDim.x * BATCH;
    int t = blockIdx.x * BATCH;
    if (t >= n_tokens) return;

    // ---- prologue: load batch 0 ----
    int   rows[BATCH];
    int4  v[BATCH];
    float sc[BATCH];
#pragma unroll
    for (int i = 0; i < BATCH; i++) {
        int tok = t + i;
        rows[i] = (tok < n_tokens) ? __ldg(x + tok) : 0;
    }
#pragma unroll
    for (int i = 0; i < BATCH; i++) {
        const int4* rp = reinterpret_cast<const int4*>(qw + (long long)rows[i] * DIM);
        v[i] = __ldg(rp + threadIdx.x);
    }
#pragma unroll
    for (int i = 0; i < BATCH; i++)
        sc[i] = __ldg(absmax + rows[i]) * (1.0f / 127.0f);

    while (true) {
        const int tn = t + stride;
        const bool have_next = (tn < n_tokens);

        // ---- prefetch batch k+1 (issued before we consume batch k) ----
        int   rows2[BATCH];
        int4  v2[BATCH];
        float sc2[BATCH];
        if (have_next) {
#pragma unroll
            for (int i = 0; i < BATCH; i++) {
                int tok = tn + i;
                rows2[i] = (tok < n_tokens) ? __ldg(x + tok) : 0;
            }
#pragma unroll
            for (int i = 0; i < BATCH; i++) {
                const int4* rp = reinterpret_cast<const int4*>(qw + (long long)rows2[i] * DIM);
                v2[i] = __ldg(rp + threadIdx.x);
            }
#pragma unroll
            for (int i = 0; i < BATCH; i++)
                sc2[i] = __ldg(absmax + rows2[i]) * (1.0f / 127.0f);
        }

        // ---- convert + store batch k (overlaps batch k+1's DRAM latency) ----
#pragma unroll
        for (int i = 0; i < BATCH; i++) {
            if (t + i >= n_tokens) break;
            float4 o;
            o.x = (float)v[i].x * sc[i];
            o.y = (float)v[i].y * sc[i];
            o.z = (float)v[i].z * sc[i];
            o.w = (float)v[i].w * sc[i];
            float4* op = reinterpret_cast<float4*>(out + (long long)(t + i) * DIM);
            __stcs(op + threadIdx.x, o);   // evict-first: output never re-read
        }

        if (!have_next) break;
#pragma unroll
        for (int i = 0; i < BATCH; i++) { rows[i] = rows2[i]; v[i] = v2[i]; sc[i] = sc2[i]; }
        t = tn;
    }
}

extern "C" void kernel_launch(void* const* d_in, const int* in_sizes, int n_in,
                              void* d_out, int out_size)
{
    // Bind by element count: qw largest, x smallest, absmax the remaining one.
    long long max_sz = -1;
    int qw_idx = -1;
    for (int i = 0; i < n_in; i++)
        if ((long long)in_sizes[i] > max_sz) { max_sz = in_sizes[i]; qw_idx = i; }

    long long min_sz = 0x7fffffffffffLL;
    int x_idx = -1;
    for (int i = 0; i < n_in; i++) {
        if (i == qw_idx) continue;
        if ((long long)in_sizes[i] < min_sz) { min_sz = in_sizes[i]; x_idx = i; }
    }
    int am_idx = -1;
    for (int i = 0; i < n_in; i++)
        if (i != qw_idx && i != x_idx) am_idx = i;

    const int*   x      = (const int*)d_in[x_idx];
    const int*   qw     = (const int*)d_in[qw_idx];
    const float* absmax = (const float*)d_in[am_idx];
    float*       out    = (float*)d_out;
    const int n_tokens  = in_sizes[x_idx];  // 32768

    int grid = CTAS;
    int max_grid = (n_tokens + BATCH - 1) / BATCH;
    if (grid > max_grid) grid = max_grid;

    bnb8_embed_kernel<<<grid, THREADS>>>(x, qw, absmax, out, n_tokens);
}